// round 13
// baseline (speedup 1.0000x reference)
#include <cuda_runtime.h>
#include <cuda_bf16.h>
#include <cstdint>
#include <cstddef>
#include <cfloat>

// Problem constants (fixed by setup_inputs).
#define B_Q    256
#define N_BANK 50000
#define DIM_S  4096
#define DIM_D  2048
#define KTOP   9

// GEMM tiling: 128(M) x 256(N) x 64(K-fp32) chunks, 8 warps of 64x64.
#define TILE_M   128
#define TILE_N   256
#define A_TILE   16384              // 128 rows x 128B (bf16, SW128)
#define B_TILE   32768              // 256 rows x 128B
#define STAGE    (A_TILE + B_TILE)  // 49152
#define OFF_INV  (2 * STAGE)        // 98304
#define SMEM_TOTAL (OFF_INV + 1024) // 99328

// Candidate machinery (top-4 per 32-col stripe, then top-16 rescored exactly)
#define NSTRIPE_PAD  1568           // 196 CTA-cols x 8 stripes
#define NCAND        16

// ---------------- static device scratch (no allocations allowed) -------------
__device__ __align__(128) float2 g_sel[(size_t)B_Q * NSTRIPE_PAD * 4];  // 12.9 MB
__device__ __align__(128) float  g_partial[B_Q];

// ---------------- PTX helpers -------------------------------------------------
__device__ __forceinline__ uint32_t smem_u32(const void* p) {
    uint32_t a;
    asm("{ .reg .u64 t; cvta.to.shared.u64 t, %1; cvt.u32.u64 %0, t; }" : "=r"(a) : "l"(p));
    return a;
}
#define LDSM4(r, addr) \
    asm volatile("ldmatrix.sync.aligned.m8n8.x4.shared.b16 {%0,%1,%2,%3}, [%4];" \
        : "=r"((r)[0]), "=r"((r)[1]), "=r"((r)[2]), "=r"((r)[3]) : "r"(addr))

#define MMA16816(d, a, b0, b1) \
    asm volatile("mma.sync.aligned.m16n8k16.row.col.f32.bf16.bf16.f32 " \
        "{%0,%1,%2,%3}, {%4,%5,%6,%7}, {%8,%9}, {%0,%1,%2,%3};" \
        : "+f"((d)[0]), "+f"((d)[1]), "+f"((d)[2]), "+f"((d)[3]) \
        : "r"((a)[0]), "r"((a)[1]), "r"((a)[2]), "r"((a)[3]), "r"(b0), "r"(b1))

#define STS128(addr, p) \
    asm volatile("st.shared.v4.b32 [%0], {%1,%2,%3,%4};" \
        :: "r"(addr), "r"((p)[0]), "r"((p)[1]), "r"((p)[2]), "r"((p)[3]))

// 8 fp32 (two float4, consecutive cols) -> 4 packed bf16x2 (16B chunk)
__device__ __forceinline__ void cvt8(float4 a, float4 b, uint32_t* p) {
    asm("cvt.rn.bf16x2.f32 %0, %1, %2;" : "=r"(p[0]) : "f"(a.y), "f"(a.x));
    asm("cvt.rn.bf16x2.f32 %0, %1, %2;" : "=r"(p[1]) : "f"(a.w), "f"(a.z));
    asm("cvt.rn.bf16x2.f32 %0, %1, %2;" : "=r"(p[2]) : "f"(b.y), "f"(b.x));
    asm("cvt.rn.bf16x2.f32 %0, %1, %2;" : "=r"(p[3]) : "f"(b.w), "f"(b.z));
}
__device__ __forceinline__ float sq8(float4 a, float4 b) {
    return a.x * a.x + a.y * a.y + a.z * a.z + a.w * a.w +
           b.x * b.x + b.y * b.y + b.z * b.z + b.w * b.w;
}

// sorted depth-4 insert (descending)
__device__ __forceinline__ void ins4(float s, int n, float* v, int* id) {
    if (s <= v[3]) return;
    v[3] = s; id[3] = n;
    for (int q = 3; q > 0; q--) {
        if (v[q] > v[q - 1]) {
            float tv = v[q]; v[q] = v[q - 1]; v[q - 1] = tv;
            int   ti = id[q]; id[q] = id[q - 1]; id[q - 1] = ti;
        } else break;
    }
}
__device__ __forceinline__ void ins_n(float s, int n, float* v, int* id, int depth) {
    if (s <= v[depth - 1]) return;
    v[depth - 1] = s; id[depth - 1] = n;
    for (int q = depth - 1; q > 0; q--) {
        if (v[q] > v[q - 1]) {
            float tv = v[q]; v[q] = v[q - 1]; v[q - 1] = tv;
            int   ti = id[q]; id[q] = id[q - 1]; id[q - 1] = ti;
        } else break;
    }
}

// one k16-step of the warp-tile MMA (stage base addresses in at/bt)
#define DO_KC(kc) { \
    uint32_t ah[4][4], bh[2][2][4]; \
    _Pragma("unroll") \
    for (int mi = 0; mi < 4; mi++) \
        LDSM4(ah[mi], at + mi * 2048 + ((((kc) * 32) + a_colx) ^ lsw)); \
    _Pragma("unroll") \
    for (int g = 0; g < 2; g++) { \
        LDSM4(bh[g][0], bt + g * 4096 + (((kc) * 32)      ^ lsw)); \
        LDSM4(bh[g][1], bt + g * 4096 + (((kc) * 32 + 16) ^ lsw)); \
    } \
    _Pragma("unroll") \
    for (int mi = 0; mi < 4; mi++) \
        _Pragma("unroll") \
        for (int ni = 0; ni < 8; ni++) \
            MMA16816(acc[mi][ni], ah[mi], bh[ni >> 2][0][ni & 3], bh[ni >> 2][1][ni & 3]); \
}

// ---------------- 1) 1-pass bf16 HMMA GEMM + fused invnorm + fused top-4 ------
__global__ __launch_bounds__(256, 1)
void gemm_hmma_kernel(const float* __restrict__ A,
                      const float* __restrict__ Bank,
                      int K)
{
    extern __shared__ char smem[];
    const uint32_t sb = smem_u32(smem);
    const int tid = threadIdx.x;
    const int w = tid >> 5, l = tid & 31;
    const int wm = w >> 2, wn = w & 3;           // warp grid 2 x 4
    const int m0 = blockIdx.x * TILE_M;
    const int n0 = blockIdx.y * TILE_N;
    const int NC = K >> 6;

    // ---- loader mapping: 8 threads/row, 32B (8 fp32) each --------------------
    const int c8 = tid & 7;                      // col octet
    const int r0 = tid >> 3;                     // 0..31 base row
    const float* Agp = A + (size_t)(m0 + r0) * K + c8 * 8;
    const size_t rstep = (size_t)32 * K;
    const float* Bgp[8];
    bool bok[8];
    #pragma unroll
    for (int it = 0; it < 8; it++) {
        const int br = n0 + r0 + 32 * it;
        bok[it] = br < N_BANK;
        Bgp[it] = Bank + (size_t)(bok[it] ? br : 0) * K + c8 * 8;
    }
    // STS target: row*128 + (16*c8 ^ ((row&7)<<4));  row&7 == r0&7 for all its
    const uint32_t sts_off = (uint32_t)(r0 * 128 + ((16 * c8) ^ ((r0 & 7) << 4)));

    // ---- ldmatrix lane bases (SW128) ------------------------------------------
    const uint32_t lsw    = (uint32_t)((l & 7) << 4);          // swizzle term
    const uint32_t a_colx = (uint32_t)((l >> 4) << 4);         // A col half
    const uint32_t a_rl   = (uint32_t)((wm * 64 + (l & 15)) * 128);
    const uint32_t b_rl   = (uint32_t)((wn * 64 + l) * 128);

    float acc[4][8][4];
    #pragma unroll
    for (int i = 0; i < 4; i++)
        #pragma unroll
        for (int j = 0; j < 8; j++)
            #pragma unroll
            for (int e = 0; e < 4; e++) acc[i][j][e] = 0.f;

    float bsum[8];
    #pragma unroll
    for (int i = 0; i < 8; i++) bsum[i] = 0.f;

    // ---- prologue: chunk 0 -> stage 0 -----------------------------------------
    {
        #pragma unroll
        for (int it = 0; it < 4; it++) {
            float4 x = *reinterpret_cast<const float4*>(Agp + it * rstep);
            float4 y = *reinterpret_cast<const float4*>(Agp + it * rstep + 4);
            uint32_t p[4]; cvt8(x, y, p);
            STS128(sb + sts_off + it * 4096, p);
        }
        #pragma unroll
        for (int it = 0; it < 8; it++) {
            float4 x = make_float4(0.f, 0.f, 0.f, 0.f), y = x;
            if (bok[it]) {
                x = *reinterpret_cast<const float4*>(Bgp[it]);
                y = *reinterpret_cast<const float4*>(Bgp[it] + 4);
            }
            bsum[it] += sq8(x, y);
            uint32_t p[4]; cvt8(x, y, p);
            STS128(sb + A_TILE + sts_off + it * 4096, p);
        }
    }
    __syncthreads();

    // ---- main loop -------------------------------------------------------------
    #pragma unroll 1
    for (int ch = 0; ch < NC; ch++) {
        const uint32_t stc = sb + (uint32_t)(ch & 1) * STAGE;
        const uint32_t stn = sb + (uint32_t)((ch + 1) & 1) * STAGE;
        const uint32_t at = stc + a_rl;
        const uint32_t bt = stc + A_TILE + b_rl;
        const bool pf = (ch + 1) < NC;
        const int k1 = (ch + 1) << 6;

        DO_KC(0)

        float4 xa[4], ya[4];
        if (pf) {
            #pragma unroll
            for (int it = 0; it < 4; it++) {
                xa[it] = *reinterpret_cast<const float4*>(Agp + k1 + it * rstep);
                ya[it] = *reinterpret_cast<const float4*>(Agp + k1 + it * rstep + 4);
            }
        }

        DO_KC(1)

        float4 xb[4], yb[4];
        if (pf) {
            #pragma unroll
            for (int it = 0; it < 4; it++) {
                uint32_t p[4]; cvt8(xa[it], ya[it], p);
                STS128(stn + sts_off + it * 4096, p);
            }
            #pragma unroll
            for (int it = 0; it < 4; it++) {
                xb[it] = make_float4(0.f, 0.f, 0.f, 0.f); yb[it] = xb[it];
                if (bok[it]) {
                    xb[it] = *reinterpret_cast<const float4*>(Bgp[it] + k1);
                    yb[it] = *reinterpret_cast<const float4*>(Bgp[it] + k1 + 4);
                }
            }
        }

        DO_KC(2)

        if (pf) {
            #pragma unroll
            for (int it = 0; it < 4; it++) {
                bsum[it] += sq8(xb[it], yb[it]);
                uint32_t p[4]; cvt8(xb[it], yb[it], p);
                STS128(stn + A_TILE + sts_off + it * 4096, p);
            }
            #pragma unroll
            for (int it = 4; it < 8; it++) {
                xb[it - 4] = make_float4(0.f, 0.f, 0.f, 0.f); yb[it - 4] = xb[it - 4];
                if (bok[it]) {
                    xb[it - 4] = *reinterpret_cast<const float4*>(Bgp[it] + k1);
                    yb[it - 4] = *reinterpret_cast<const float4*>(Bgp[it] + k1 + 4);
                }
            }
        }

        DO_KC(3)

        if (pf) {
            #pragma unroll
            for (int it = 4; it < 8; it++) {
                bsum[it] += sq8(xb[it - 4], yb[it - 4]);
                uint32_t p[4]; cvt8(xb[it - 4], yb[it - 4], p);
                STS128(stn + A_TILE + sts_off + it * 4096, p);
            }
        }
        __syncthreads();
    }

    // ---- per-row inverse norms (8 lanes per row: xor 1,2,4) --------------------
    float* s_inv = reinterpret_cast<float*>(smem + OFF_INV);
    #pragma unroll
    for (int it = 0; it < 8; it++) {
        float v = bsum[it];
        v += __shfl_xor_sync(0xffffffffu, v, 1);
        v += __shfl_xor_sync(0xffffffffu, v, 2);
        v += __shfl_xor_sync(0xffffffffu, v, 4);
        if (c8 == 0)
            s_inv[r0 + 32 * it] = (v > 0.f) ? rsqrtf(v) : 0.f;
    }
    __syncthreads();

    // ---- epilogue: per-(row, 32-col stripe) top-4 of scaled scores -------------
    {
        const int qr = l >> 2;
        const int qc = (l & 3) * 2;
        #pragma unroll
        for (int mi = 0; mi < 4; mi++) {
            #pragma unroll
            for (int h = 0; h < 2; h++) {
                #pragma unroll
                for (int s = 0; s < 2; s++) {
                    float v[4]; int id[4];
                    #pragma unroll
                    for (int j = 0; j < 4; j++) { v[j] = -FLT_MAX; id[j] = 0; }
                    #pragma unroll
                    for (int nj = 0; nj < 4; nj++) {
                        const int ni = s * 4 + nj;
                        const int nloc = wn * 64 + ni * 8 + qc;
                        const int ng = n0 + nloc;
                        const float* d = acc[mi][ni];
                        float s0 = (ng     < N_BANK) ? d[2 * h]     * s_inv[nloc]     : -FLT_MAX;
                        float s1 = (ng + 1 < N_BANK) ? d[2 * h + 1] * s_inv[nloc + 1] : -FLT_MAX;
                        ins4(s0, ng,     v, id);
                        ins4(s1, ng + 1, v, id);
                    }
                    #pragma unroll
                    for (int o = 1; o <= 2; o <<= 1) {
                        float tv[4]; int ti[4];
                        #pragma unroll
                        for (int j = 0; j < 4; j++) { tv[j] = v[j]; ti[j] = id[j]; }
                        #pragma unroll
                        for (int j = 0; j < 4; j++) {
                            float ov = __shfl_xor_sync(0xffffffffu, tv[j], o);
                            int   oi = __shfl_xor_sync(0xffffffffu, ti[j], o);
                            ins4(ov, oi, v, id);
                        }
                    }
                    if ((l & 3) == 0) {
                        const int row = m0 + wm * 64 + mi * 16 + qr + 8 * h;
                        const int stripe = blockIdx.y * 8 + wn * 2 + s;
                        float2* dst = g_sel + ((size_t)row * NSTRIPE_PAD + stripe) * 4;
                        #pragma unroll
                        for (int j = 0; j < 4; j++)
                            dst[j] = make_float2(v[j], __int_as_float(id[j]));
                    }
                }
            }
        }
    }
}

// ---------------- 2) fused final select (top-16) + exact rescore + top-9 ------
__global__ __launch_bounds__(512)
void finalsel_kernel(const float* __restrict__ A,
                     const float* __restrict__ Bank,
                     int K,
                     const float* __restrict__ metrics,
                     float* __restrict__ out,
                     int phase)
{
    __shared__ float sv[512 * 4];
    __shared__ int   si[512 * 4];
    __shared__ float sv2[32 * 8];
    __shared__ int   si2[32 * 8];
    __shared__ float cv[NCAND];
    __shared__ int   ci[NCAND];
    __shared__ float ss[NCAND];

    const int row = blockIdx.x;
    const int tid = threadIdx.x;

    // phase 1: per-thread top-4 (2 entries per float4)
    const float4* base4 = reinterpret_cast<const float4*>(
        g_sel + (size_t)row * NSTRIPE_PAD * 4);
    const int nf4 = NSTRIPE_PAD * 4 / 2;      // 3136

    float v[4]; int id[4];
    #pragma unroll
    for (int j = 0; j < 4; j++) { v[j] = -FLT_MAX; id[j] = 0; }
    for (int i = tid; i < nf4; i += 512) {
        float4 x = base4[i];
        ins4(x.x, __float_as_int(x.y), v, id);
        ins4(x.z, __float_as_int(x.w), v, id);
    }
    #pragma unroll
    for (int j = 0; j < 4; j++) { sv[tid * 4 + j] = v[j]; si[tid * 4 + j] = id[j]; }
    __syncthreads();

    // phase 2: warp-0 funnel 2048 -> 256
    if (tid < 32) {
        float mv[8]; int mi[8];
        #pragma unroll
        for (int j = 0; j < 8; j++) { mv[j] = -FLT_MAX; mi[j] = 0; }
        for (int e = tid; e < 2048; e += 32)
            ins_n(sv[e], si[e], mv, mi, 8);
        #pragma unroll
        for (int j = 0; j < 8; j++) { sv2[tid * 8 + j] = mv[j]; si2[tid * 8 + j] = mi[j]; }
    }
    __syncthreads();

    // phase 3: thread 0 -> global top-16 candidates
    if (tid == 0) {
        float mv[NCAND]; int mi[NCAND];
        #pragma unroll
        for (int j = 0; j < NCAND; j++) { mv[j] = -FLT_MAX; mi[j] = 0; }
        for (int e = 0; e < 256; e++)
            ins_n(sv2[e], si2[e], mv, mi, NCAND);
        #pragma unroll
        for (int j = 0; j < NCAND; j++) { cv[j] = mv[j]; ci[j] = mi[j]; }
    }
    __syncthreads();

    // phase 4: exact fp32 rescore, one candidate per warp (16 warps)
    {
        const int wp = tid >> 5, l = tid & 31;
        const float4* q4 = reinterpret_cast<const float4*>(A + (size_t)row * K);
        const int kv = K >> 2;
        const int idx = ci[wp];
        const float4* b4 = reinterpret_cast<const float4*>(Bank + (size_t)idx * K);
        float dot = 0.f, bsq = 0.f;
        for (int i = l; i < kv; i += 32) {
            float4 b = b4[i], q = q4[i];
            dot += q.x * b.x + q.y * b.y + q.z * b.z + q.w * b.w;
            bsq += b.x * b.x + b.y * b.y + b.z * b.z + b.w * b.w;
        }
        #pragma unroll
        for (int o = 16; o; o >>= 1) {
            dot += __shfl_xor_sync(0xffffffffu, dot, o);
            bsq += __shfl_xor_sync(0xffffffffu, bsq, o);
        }
        if (l == 0) ss[wp] = dot * rsqrtf(bsq);
    }
    __syncthreads();

    // phase 5: exact top-9 + metrics mean
    if (tid == 0) {
        float v9[KTOP]; int id9[KTOP];
        #pragma unroll
        for (int j = 0; j < KTOP; j++) { v9[j] = -FLT_MAX; id9[j] = 0; }
        #pragma unroll
        for (int c = 0; c < NCAND; c++)
            ins_n(ss[c], ci[c], v9, id9, KTOP);
        float ssum = 0.f;
        #pragma unroll
        for (int j = 0; j < KTOP; j++) ssum += metrics[id9[j]];
        if (phase == 0) g_partial[row] = ssum;
        else            out[row] = (g_partial[row] + ssum) * (1.f / (2.f * KTOP));
    }
}

// ---------------- launch ------------------------------------------------------
extern "C" void kernel_launch(void* const* d_in, const int* in_sizes, int n_in,
                              void* d_out, int out_size) {
    const float* f_content    = nullptr;
    const float* f_distorsion = nullptr;
    const float* sem_bank     = nullptr;
    const float* dst_bank     = nullptr;
    const float* metrics      = nullptr;
    for (int i = 0; i < n_in; i++) {
        switch (in_sizes[i]) {
            case B_Q * DIM_S:    f_content    = (const float*)d_in[i]; break;
            case B_Q * DIM_D:    f_distorsion = (const float*)d_in[i]; break;
            case N_BANK * DIM_S: sem_bank     = (const float*)d_in[i]; break;
            case N_BANK * DIM_D: dst_bank     = (const float*)d_in[i]; break;
            case N_BANK:         metrics      = (const float*)d_in[i]; break;
            default: break; // scalar K (=9) compiled in
        }
    }
    float* out = (float*)d_out;

    cudaFuncSetAttribute(gemm_hmma_kernel,
                         cudaFuncAttributeMaxDynamicSharedMemorySize, SMEM_TOTAL);

    dim3 grid(B_Q / TILE_M, (N_BANK + TILE_N - 1) / TILE_N);   // (2, 196), m-fastest

    // semantic branch
    gemm_hmma_kernel<<<grid, 256, SMEM_TOTAL>>>(f_content, sem_bank, DIM_S);
    finalsel_kernel<<<B_Q, 512>>>(f_content, sem_bank, DIM_S, metrics, out, 0);

    // distorsion branch (reuses g_sel)
    gemm_hmma_kernel<<<grid, 256, SMEM_TOTAL>>>(f_distorsion, dst_bank, DIM_D);
    finalsel_kernel<<<B_Q, 512>>>(f_distorsion, dst_bank, DIM_D, metrics, out, 1);
}

// round 14
// speedup vs baseline: 1.0205x; 1.0205x over previous
#include <cuda_runtime.h>
#include <cuda_bf16.h>
#include <cstdint>
#include <cstddef>
#include <cfloat>

// Problem constants (fixed by setup_inputs).
#define B_Q    256
#define N_BANK 50000
#define DIM_S  4096
#define DIM_D  2048
#define KTOP   9

// GEMM tiling: 128(M) x 256(N) x 32(K-fp32) chunks, 8 warps of 64x64.
#define TILE_M   128
#define TILE_N   256
#define T_STRIDE 80                 // bytes per bf16 tile row (64B data + 16B pad)
#define A_TILE   (128 * T_STRIDE)   // 10240
#define B_TILE   (256 * T_STRIDE)   // 20480
#define STAGE    (A_TILE + B_TILE)  // 30720
#define OFF_INV  (2 * STAGE)        // 61440
#define SMEM_TOTAL (OFF_INV + 1024) // 62464

// Candidate machinery (top-4 per 32-col stripe, then top-16 rescored exactly)
#define NSTRIPE_PAD  1568           // 196 CTA-cols x 8 stripes
#define NCAND        16

// ---------------- static device scratch (no allocations allowed) -------------
__device__ __align__(128) float2 g_sel[(size_t)B_Q * NSTRIPE_PAD * 4];  // 12.9 MB
__device__ __align__(128) float  g_partial[B_Q];

// ---------------- PTX helpers -------------------------------------------------
__device__ __forceinline__ uint32_t smem_u32(const void* p) {
    uint32_t a;
    asm("{ .reg .u64 t; cvta.to.shared.u64 t, %1; cvt.u32.u64 %0, t; }" : "=r"(a) : "l"(p));
    return a;
}
__device__ __forceinline__ void sts64(uint32_t addr, uint32_t a, uint32_t b) {
    asm volatile("st.shared.v2.b32 [%0], {%1,%2};" :: "r"(addr), "r"(a), "r"(b));
}
#define LDSM4(r, addr) \
    asm volatile("ldmatrix.sync.aligned.m8n8.x4.shared.b16 {%0,%1,%2,%3}, [%4];" \
        : "=r"((r)[0]), "=r"((r)[1]), "=r"((r)[2]), "=r"((r)[3]) : "r"(addr))

#define MMA16816(d, a, b0, b1) \
    asm volatile("mma.sync.aligned.m16n8k16.row.col.f32.bf16.bf16.f32 " \
        "{%0,%1,%2,%3}, {%4,%5,%6,%7}, {%8,%9}, {%0,%1,%2,%3};" \
        : "+f"((d)[0]), "+f"((d)[1]), "+f"((d)[2]), "+f"((d)[3]) \
        : "r"((a)[0]), "r"((a)[1]), "r"((a)[2]), "r"((a)[3]), "r"(b0), "r"(b1))

// float4 -> two packed bf16x2 (low 16 bits = lower column)
__device__ __forceinline__ void cvt_hi(float4 v, uint32_t& h0, uint32_t& h1) {
    asm("cvt.rn.bf16x2.f32 %0, %1, %2;" : "=r"(h0) : "f"(v.y), "f"(v.x));
    asm("cvt.rn.bf16x2.f32 %0, %1, %2;" : "=r"(h1) : "f"(v.w), "f"(v.z));
}
__device__ __forceinline__ float sq4(float4 a) {
    return a.x * a.x + a.y * a.y + a.z * a.z + a.w * a.w;
}

// sorted depth-4 insert (descending)
__device__ __forceinline__ void ins4(float s, int n, float* v, int* id) {
    if (s <= v[3]) return;
    v[3] = s; id[3] = n;
    for (int q = 3; q > 0; q--) {
        if (v[q] > v[q - 1]) {
            float tv = v[q]; v[q] = v[q - 1]; v[q - 1] = tv;
            int   ti = id[q]; id[q] = id[q - 1]; id[q - 1] = ti;
        } else break;
    }
}
__device__ __forceinline__ void ins_n(float s, int n, float* v, int* id, int depth) {
    if (s <= v[depth - 1]) return;
    v[depth - 1] = s; id[depth - 1] = n;
    for (int q = depth - 1; q > 0; q--) {
        if (v[q] > v[q - 1]) {
            float tv = v[q]; v[q] = v[q - 1]; v[q - 1] = tv;
            int   ti = id[q]; id[q] = id[q - 1]; id[q - 1] = ti;
        } else break;
    }
}

// one k16-step of the 64x64 warp-tile MMA (stage bases in at/bt)
#define DO_KC(kc) { \
    uint32_t ah[4][4], bh[2][2][4]; \
    _Pragma("unroll") \
    for (int mi = 0; mi < 4; mi++) \
        LDSM4(ah[mi], at + (uint32_t)(mi * 16 * T_STRIDE) + a_colk + (kc) * 32); \
    _Pragma("unroll") \
    for (int g = 0; g < 2; g++) { \
        LDSM4(bh[g][0], bt + (uint32_t)(g * 32 * T_STRIDE) + (kc) * 32); \
        LDSM4(bh[g][1], bt + (uint32_t)(g * 32 * T_STRIDE) + (kc) * 32 + 16); \
    } \
    _Pragma("unroll") \
    for (int mi = 0; mi < 4; mi++) \
        _Pragma("unroll") \
        for (int ni = 0; ni < 8; ni++) \
            MMA16816(acc[mi][ni], ah[mi], bh[ni >> 2][0][ni & 3], bh[ni >> 2][1][ni & 3]); \
}

// ---------------- 1) 1-pass bf16 HMMA GEMM + fused invnorm + fused top-4 ------
__global__ __launch_bounds__(256, 1)
void gemm_hmma_kernel(const float* __restrict__ A,
                      const float* __restrict__ Bank,
                      int K)
{
    extern __shared__ char smem[];
    const uint32_t sb = smem_u32(smem);
    const int tid = threadIdx.x;
    const int w = tid >> 5, l = tid & 31;
    const int wm = w >> 2, wn = w & 3;           // warp grid 2 x 4
    const int m0 = blockIdx.x * TILE_M;
    const int n0 = blockIdx.y * TILE_N;
    const int NC = K >> 5;

    // ---- loader: 8 threads/row, one float4 (16B) each; A 4 groups, B 8 groups
    const int c8 = tid & 7;
    const int r0 = tid >> 3;                     // 0..31
    const float* Agp = A + (size_t)(m0 + r0) * K + c8 * 4;
    const float* Bgp = Bank + (size_t)(n0 + r0) * K + c8 * 4;
    const size_t rstep = (size_t)32 * K;
    bool bok[8];
    #pragma unroll
    for (int it = 0; it < 8; it++) bok[it] = (n0 + r0 + 32 * it) < N_BANK;
    const uint32_t sts_off = (uint32_t)(r0 * T_STRIDE + c8 * 8);

    // ---- ldmatrix lane bases ---------------------------------------------------
    const uint32_t a_base = (uint32_t)((wm * 64 + (l & 15)) * T_STRIDE);
    const uint32_t a_colk = (uint32_t)((l >> 4) << 4);
    const uint32_t b_base = (uint32_t)((wn * 64 + l) * T_STRIDE);

    float acc[4][8][4];
    #pragma unroll
    for (int i = 0; i < 4; i++)
        #pragma unroll
        for (int j = 0; j < 8; j++)
            #pragma unroll
            for (int e = 0; e < 4; e++) acc[i][j][e] = 0.f;

    float bsum[8];
    #pragma unroll
    for (int i = 0; i < 8; i++) bsum[i] = 0.f;

    // ---- prologue: chunk 0 -> stage 0 -------------------------------------------
    {
        #pragma unroll
        for (int it = 0; it < 4; it++) {
            float4 v = *reinterpret_cast<const float4*>(Agp + it * rstep);
            uint32_t h0, h1; cvt_hi(v, h0, h1);
            sts64(sb + sts_off + (uint32_t)(it * 32 * T_STRIDE), h0, h1);
        }
        #pragma unroll
        for (int it = 0; it < 8; it++) {
            float4 v = bok[it] ? *reinterpret_cast<const float4*>(Bgp + it * rstep)
                               : make_float4(0.f, 0.f, 0.f, 0.f);
            bsum[it] += sq4(v);
            uint32_t h0, h1; cvt_hi(v, h0, h1);
            sts64(sb + A_TILE + sts_off + (uint32_t)(it * 32 * T_STRIDE), h0, h1);
        }
    }
    __syncthreads();

    // ---- main loop ----------------------------------------------------------------
    #pragma unroll 1
    for (int ch = 0; ch < NC; ch++) {
        const uint32_t stc = sb + (uint32_t)(ch & 1) * STAGE;
        const uint32_t stn = sb + (uint32_t)((ch + 1) & 1) * STAGE;
        const uint32_t at = stc + a_base;
        const uint32_t bt = stc + A_TILE + b_base;
        const bool pf = (ch + 1) < NC;
        const int k1 = (ch + 1) << 5;

        // prefetch group 1: A(4) + B(0..3)
        float4 av[4], bv0[4];
        if (pf) {
            #pragma unroll
            for (int it = 0; it < 4; it++)
                av[it] = *reinterpret_cast<const float4*>(Agp + k1 + it * rstep);
            #pragma unroll
            for (int it = 0; it < 4; it++)
                bv0[it] = bok[it] ? *reinterpret_cast<const float4*>(Bgp + k1 + it * rstep)
                                  : make_float4(0.f, 0.f, 0.f, 0.f);
        }

        DO_KC(0)

        // prefetch group 2: B(4..7); store group 1
        float4 bv1[4];
        if (pf) {
            #pragma unroll
            for (int it = 0; it < 4; it++)
                bv1[it] = bok[it + 4]
                    ? *reinterpret_cast<const float4*>(Bgp + k1 + (it + 4) * rstep)
                    : make_float4(0.f, 0.f, 0.f, 0.f);
            #pragma unroll
            for (int it = 0; it < 4; it++) {
                uint32_t h0, h1; cvt_hi(av[it], h0, h1);
                sts64(stn + sts_off + (uint32_t)(it * 32 * T_STRIDE), h0, h1);
            }
            #pragma unroll
            for (int it = 0; it < 4; it++) {
                bsum[it] += sq4(bv0[it]);
                uint32_t h0, h1; cvt_hi(bv0[it], h0, h1);
                sts64(stn + A_TILE + sts_off + (uint32_t)(it * 32 * T_STRIDE), h0, h1);
            }
        }

        DO_KC(1)

        if (pf) {
            #pragma unroll
            for (int it = 0; it < 4; it++) {
                bsum[it + 4] += sq4(bv1[it]);
                uint32_t h0, h1; cvt_hi(bv1[it], h0, h1);
                sts64(stn + A_TILE + sts_off + (uint32_t)((it + 4) * 32 * T_STRIDE), h0, h1);
            }
        }
        __syncthreads();
    }

    // ---- per-row inverse norms (8 lanes per row: xor 1,2,4) ------------------------
    float* s_inv = reinterpret_cast<float*>(smem + OFF_INV);
    #pragma unroll
    for (int it = 0; it < 8; it++) {
        float v = bsum[it];
        v += __shfl_xor_sync(0xffffffffu, v, 1);
        v += __shfl_xor_sync(0xffffffffu, v, 2);
        v += __shfl_xor_sync(0xffffffffu, v, 4);
        if (c8 == 0)
            s_inv[r0 + 32 * it] = (v > 0.f) ? rsqrtf(v) : 0.f;
    }
    __syncthreads();

    // ---- epilogue: per-(row, 32-col stripe) top-4 of scaled scores -----------------
    {
        const int qr = l >> 2;
        const int qc = (l & 3) * 2;
        #pragma unroll
        for (int mi = 0; mi < 4; mi++) {
            #pragma unroll
            for (int h = 0; h < 2; h++) {
                #pragma unroll
                for (int s = 0; s < 2; s++) {
                    float v[4]; int id[4];
                    #pragma unroll
                    for (int j = 0; j < 4; j++) { v[j] = -FLT_MAX; id[j] = 0; }
                    #pragma unroll
                    for (int nj = 0; nj < 4; nj++) {
                        const int ni = s * 4 + nj;
                        const int nloc = wn * 64 + s * 32 + nj * 8 + qc;
                        const int ng = n0 + nloc;
                        const float* d = acc[mi][ni];
                        float s0 = (ng     < N_BANK) ? d[2 * h]     * s_inv[nloc]     : -FLT_MAX;
                        float s1 = (ng + 1 < N_BANK) ? d[2 * h + 1] * s_inv[nloc + 1] : -FLT_MAX;
                        ins4(s0, ng,     v, id);
                        ins4(s1, ng + 1, v, id);
                    }
                    #pragma unroll
                    for (int o = 1; o <= 2; o <<= 1) {
                        float tv[4]; int ti[4];
                        #pragma unroll
                        for (int j = 0; j < 4; j++) { tv[j] = v[j]; ti[j] = id[j]; }
                        #pragma unroll
                        for (int j = 0; j < 4; j++) {
                            float ov = __shfl_xor_sync(0xffffffffu, tv[j], o);
                            int   oi = __shfl_xor_sync(0xffffffffu, ti[j], o);
                            ins4(ov, oi, v, id);
                        }
                    }
                    if ((l & 3) == 0) {
                        const int row = m0 + wm * 64 + mi * 16 + qr + 8 * h;
                        const int stripe = blockIdx.y * 8 + wn * 2 + s;
                        float2* dst = g_sel + ((size_t)row * NSTRIPE_PAD + stripe) * 4;
                        #pragma unroll
                        for (int j = 0; j < 4; j++)
                            dst[j] = make_float2(v[j], __int_as_float(id[j]));
                    }
                }
            }
        }
    }
}

// ---------------- 2) fused final select (top-16) + exact rescore + top-9 ------
__global__ void finalsel_kernel(const float* __restrict__ A,
                                const float* __restrict__ Bank,
                                int K,
                                const float* __restrict__ metrics,
                                float* __restrict__ out,
                                int phase)
{
    __shared__ float sv[256 * 4];
    __shared__ int   si[256 * 4];
    __shared__ float sv2[32 * 8];
    __shared__ int   si2[32 * 8];
    __shared__ float cv[NCAND];
    __shared__ int   ci[NCAND];
    __shared__ float ss[NCAND];

    const int row = blockIdx.x;
    const int tid = threadIdx.x;

    // phase 1: per-thread top-4 (2 entries per float4)
    const float4* base4 = reinterpret_cast<const float4*>(
        g_sel + (size_t)row * NSTRIPE_PAD * 4);
    const int nf4 = NSTRIPE_PAD * 4 / 2;      // 3136

    float v[4]; int id[4];
    #pragma unroll
    for (int j = 0; j < 4; j++) { v[j] = -FLT_MAX; id[j] = 0; }
    for (int i = tid; i < nf4; i += 256) {
        float4 x = base4[i];
        ins4(x.x, __float_as_int(x.y), v, id);
        ins4(x.z, __float_as_int(x.w), v, id);
    }
    #pragma unroll
    for (int j = 0; j < 4; j++) { sv[tid * 4 + j] = v[j]; si[tid * 4 + j] = id[j]; }
    __syncthreads();

    // phase 2: warp-0 funnel 1024 -> 256
    if (tid < 32) {
        float mv[8]; int mi[8];
        #pragma unroll
        for (int j = 0; j < 8; j++) { mv[j] = -FLT_MAX; mi[j] = 0; }
        for (int e = tid; e < 1024; e += 32)
            ins_n(sv[e], si[e], mv, mi, 8);
        #pragma unroll
        for (int j = 0; j < 8; j++) { sv2[tid * 8 + j] = mv[j]; si2[tid * 8 + j] = mi[j]; }
    }
    __syncthreads();

    // phase 3: thread 0 -> global top-16 candidates
    if (tid == 0) {
        float mv[NCAND]; int mi[NCAND];
        #pragma unroll
        for (int j = 0; j < NCAND; j++) { mv[j] = -FLT_MAX; mi[j] = 0; }
        for (int e = 0; e < 256; e++)
            ins_n(sv2[e], si2[e], mv, mi, NCAND);
        #pragma unroll
        for (int j = 0; j < NCAND; j++) { cv[j] = mv[j]; ci[j] = mi[j]; }
    }
    __syncthreads();

    // phase 4: exact fp32 rescore of 16 candidates (2 per warp)
    {
        const int wp = tid >> 5, l = tid & 31;
        const float4* q4 = reinterpret_cast<const float4*>(A + (size_t)row * K);
        const int kv = K >> 2;
        for (int c = wp; c < NCAND; c += 8) {
            const int idx = ci[c];
            const float4* b4 = reinterpret_cast<const float4*>(Bank + (size_t)idx * K);
            float dot = 0.f, bsq = 0.f;
            for (int i = l; i < kv; i += 32) {
                float4 b = b4[i], q = q4[i];
                dot += q.x * b.x + q.y * b.y + q.z * b.z + q.w * b.w;
                bsq += b.x * b.x + b.y * b.y + b.z * b.z + b.w * b.w;
            }
            #pragma unroll
            for (int o = 16; o; o >>= 1) {
                dot += __shfl_xor_sync(0xffffffffu, dot, o);
                bsq += __shfl_xor_sync(0xffffffffu, bsq, o);
            }
            if (l == 0) ss[c] = dot * rsqrtf(bsq);
        }
    }
    __syncthreads();

    // phase 5: exact top-9 + metrics mean
    if (tid == 0) {
        float v9[KTOP]; int id9[KTOP];
        #pragma unroll
        for (int j = 0; j < KTOP; j++) { v9[j] = -FLT_MAX; id9[j] = 0; }
        #pragma unroll
        for (int c = 0; c < NCAND; c++)
            ins_n(ss[c], ci[c], v9, id9, KTOP);
        float ssum = 0.f;
        #pragma unroll
        for (int j = 0; j < KTOP; j++) ssum += metrics[id9[j]];
        if (phase == 0) g_partial[row] = ssum;
        else            out[row] = (g_partial[row] + ssum) * (1.f / (2.f * KTOP));
    }
}

// ---------------- launch ------------------------------------------------------
extern "C" void kernel_launch(void* const* d_in, const int* in_sizes, int n_in,
                              void* d_out, int out_size) {
    const float* f_content    = nullptr;
    const float* f_distorsion = nullptr;
    const float* sem_bank     = nullptr;
    const float* dst_bank     = nullptr;
    const float* metrics      = nullptr;
    for (int i = 0; i < n_in; i++) {
        switch (in_sizes[i]) {
            case B_Q * DIM_S:    f_content    = (const float*)d_in[i]; break;
            case B_Q * DIM_D:    f_distorsion = (const float*)d_in[i]; break;
            case N_BANK * DIM_S: sem_bank     = (const float*)d_in[i]; break;
            case N_BANK * DIM_D: dst_bank     = (const float*)d_in[i]; break;
            case N_BANK:         metrics      = (const float*)d_in[i]; break;
            default: break; // scalar K (=9) compiled in
        }
    }
    float* out = (float*)d_out;

    cudaFuncSetAttribute(gemm_hmma_kernel,
                         cudaFuncAttributeMaxDynamicSharedMemorySize, SMEM_TOTAL);

    dim3 grid(B_Q / TILE_M, (N_BANK + TILE_N - 1) / TILE_N);   // (2, 196), m-fastest

    // semantic branch
    gemm_hmma_kernel<<<grid, 256, SMEM_TOTAL>>>(f_content, sem_bank, DIM_S);
    finalsel_kernel<<<B_Q, 256>>>(f_content, sem_bank, DIM_S, metrics, out, 0);

    // distorsion branch (reuses g_sel)
    gemm_hmma_kernel<<<grid, 256, SMEM_TOTAL>>>(f_distorsion, dst_bank, DIM_D);
    finalsel_kernel<<<B_Q, 256>>>(f_distorsion, dst_bank, DIM_D, metrics, out, 1);
}

// round 15
// speedup vs baseline: 1.6263x; 1.5937x over previous
#include <cuda_runtime.h>
#include <cuda_bf16.h>
#include <cstdint>
#include <cstddef>
#include <cfloat>

// Problem constants (fixed by setup_inputs).
#define B_Q    256
#define N_BANK 50000
#define DIM_S  4096
#define DIM_D  2048
#define KTOP   9

// GEMM tiling: proven 920us shape. 128(M) x 128(N) x 32(K-fp32), 8 warps 64x32.
#define TILE_M   128
#define TILE_N   128
#define T_STRIDE 80                 // bytes per bf16 tile row (64B data + 16B pad)
#define A_TILE   (128 * T_STRIDE)   // 10240
#define B_TILE   (128 * T_STRIDE)   // 10240
#define STAGE    (A_TILE + B_TILE)  // 20480
#define OFF_INV  (2 * STAGE)        // 40960
#define SMEM_TOTAL (OFF_INV + 512)  // 41472  (x2 CTAs/SM = 83KB)

// Candidate machinery (top-4 per 32-col stripe -> top-16 -> exact rescore)
#define NSTRIPE_PAD  1568           // 391 CTA-cols x 4 stripes = 1564, padded
#define NCAND        16
#define SELSZ  ((size_t)B_Q * NSTRIPE_PAD * 4)

// ---------------- static device scratch (no allocations allowed) -------------
__device__ __align__(128) float2 g_sel[2 * SELSZ];   // 25.7 MB (per-branch)

// ---------------- PTX helpers -------------------------------------------------
__device__ __forceinline__ uint32_t smem_u32(const void* p) {
    uint32_t a;
    asm("{ .reg .u64 t; cvta.to.shared.u64 t, %1; cvt.u32.u64 %0, t; }" : "=r"(a) : "l"(p));
    return a;
}
__device__ __forceinline__ void sts64(uint32_t addr, uint32_t a, uint32_t b) {
    asm volatile("st.shared.v2.b32 [%0], {%1,%2};" :: "r"(addr), "r"(a), "r"(b));
}
#define LDSM4(r, addr) \
    asm volatile("ldmatrix.sync.aligned.m8n8.x4.shared.b16 {%0,%1,%2,%3}, [%4];" \
        : "=r"((r)[0]), "=r"((r)[1]), "=r"((r)[2]), "=r"((r)[3]) : "r"(addr))

#define MMA16816(d, a, b0, b1) \
    asm volatile("mma.sync.aligned.m16n8k16.row.col.f32.bf16.bf16.f32 " \
        "{%0,%1,%2,%3}, {%4,%5,%6,%7}, {%8,%9}, {%0,%1,%2,%3};" \
        : "+f"((d)[0]), "+f"((d)[1]), "+f"((d)[2]), "+f"((d)[3]) \
        : "r"((a)[0]), "r"((a)[1]), "r"((a)[2]), "r"((a)[3]), "r"(b0), "r"(b1))

// float4 -> two packed bf16x2 (low 16 bits = lower column)
__device__ __forceinline__ void cvt_hi(float4 v, uint32_t& h0, uint32_t& h1) {
    asm("cvt.rn.bf16x2.f32 %0, %1, %2;" : "=r"(h0) : "f"(v.y), "f"(v.x));
    asm("cvt.rn.bf16x2.f32 %0, %1, %2;" : "=r"(h1) : "f"(v.w), "f"(v.z));
}
__device__ __forceinline__ float sq4(float4 a) {
    return a.x * a.x + a.y * a.y + a.z * a.z + a.w * a.w;
}

// sorted depth-4 insert (descending)
__device__ __forceinline__ void ins4(float s, int n, float* v, int* id) {
    if (s <= v[3]) return;
    v[3] = s; id[3] = n;
    for (int q = 3; q > 0; q--) {
        if (v[q] > v[q - 1]) {
            float tv = v[q]; v[q] = v[q - 1]; v[q - 1] = tv;
            int   ti = id[q]; id[q] = id[q - 1]; id[q - 1] = ti;
        } else break;
    }
}
__device__ __forceinline__ void ins_n(float s, int n, float* v, int* id, int depth) {
    if (s <= v[depth - 1]) return;
    v[depth - 1] = s; id[depth - 1] = n;
    for (int q = depth - 1; q > 0; q--) {
        if (v[q] > v[q - 1]) {
            float tv = v[q]; v[q] = v[q - 1]; v[q - 1] = tv;
            int   ti = id[q]; id[q] = id[q - 1]; id[q - 1] = ti;
        } else break;
    }
}

// one k16-step of the 64x32 warp-tile MMA
#define DO_KC(kc) { \
    uint32_t ah[4][4], bh[2][4]; \
    _Pragma("unroll") \
    for (int mi = 0; mi < 4; mi++) \
        LDSM4(ah[mi], at + (uint32_t)(mi * 16 * T_STRIDE) + a_colk + (kc) * 32); \
    LDSM4(bh[0], bt + (kc) * 32); \
    LDSM4(bh[1], bt + (kc) * 32 + 16); \
    _Pragma("unroll") \
    for (int mi = 0; mi < 4; mi++) \
        _Pragma("unroll") \
        for (int ni = 0; ni < 4; ni++) \
            MMA16816(acc[mi][ni], ah[mi], bh[0][ni], bh[1][ni]); \
}

// ---------------- 1) 1-pass bf16 HMMA GEMM, both branches in one launch -------
__global__ __launch_bounds__(256, 2)
void gemm_hmma_kernel(const float* __restrict__ fc, const float* __restrict__ sem,
                      const float* __restrict__ fd, const float* __restrict__ dst)
{
    extern __shared__ char smem[];
    const uint32_t sb = smem_u32(smem);
    const int br = blockIdx.z;
    const float* __restrict__ A    = br ? fd  : fc;
    const float* __restrict__ Bank = br ? dst : sem;
    const int K = br ? DIM_D : DIM_S;
    float2* __restrict__ selb = g_sel + (size_t)br * SELSZ;

    const int tid = threadIdx.x;
    const int w = tid >> 5, l = tid & 31;
    const int wm = w >> 2, wn = w & 3;           // warp grid 2 x 4 (64x32 tiles)
    const int m0 = blockIdx.x * TILE_M;
    const int n0 = blockIdx.y * TILE_N;
    const int NC = K >> 5;

    // ---- coalesced loader: 8 threads/row, one float4 each; 4 A + 4 B groups --
    const int c8 = tid & 7;
    const int r0 = tid >> 3;                     // 0..31
    const float* Agp = A + (size_t)(m0 + r0) * K + c8 * 4;
    const float* Bgp = Bank + (size_t)(n0 + r0) * K + c8 * 4;   // n0+r0 < 50000 always
    const size_t rstep = (size_t)32 * K;
    bool bok[4];
    #pragma unroll
    for (int it = 0; it < 4; it++) bok[it] = (n0 + r0 + 32 * it) < N_BANK;
    const uint32_t sts_off = (uint32_t)(r0 * T_STRIDE + c8 * 8);

    // ---- ldmatrix lane bases ----------------------------------------------------
    const uint32_t a_base = (uint32_t)((wm * 64 + (l & 15)) * T_STRIDE);
    const uint32_t a_colk = (uint32_t)((l >> 4) << 4);
    const uint32_t b_base = (uint32_t)((wn * 32 + l) * T_STRIDE);

    float acc[4][4][4];
    #pragma unroll
    for (int i = 0; i < 4; i++)
        #pragma unroll
        for (int j = 0; j < 4; j++)
            #pragma unroll
            for (int e = 0; e < 4; e++) acc[i][j][e] = 0.f;

    float bsum[4] = {0.f, 0.f, 0.f, 0.f};

    // ---- prologue: chunk 0 -> stage 0 ---------------------------------------------
    {
        #pragma unroll
        for (int it = 0; it < 4; it++) {
            float4 v = *reinterpret_cast<const float4*>(Agp + it * rstep);
            uint32_t h0, h1; cvt_hi(v, h0, h1);
            sts64(sb + sts_off + (uint32_t)(it * 32 * T_STRIDE), h0, h1);
        }
        #pragma unroll
        for (int it = 0; it < 4; it++) {
            float4 v = bok[it] ? *reinterpret_cast<const float4*>(Bgp + it * rstep)
                               : make_float4(0.f, 0.f, 0.f, 0.f);
            bsum[it] += sq4(v);
            uint32_t h0, h1; cvt_hi(v, h0, h1);
            sts64(sb + A_TILE + sts_off + (uint32_t)(it * 32 * T_STRIDE), h0, h1);
        }
    }
    __syncthreads();

    // ---- main loop --------------------------------------------------------------
    #pragma unroll 1
    for (int ch = 0; ch < NC; ch++) {
        const uint32_t stc = sb + (uint32_t)(ch & 1) * STAGE;
        const uint32_t stn = sb + (uint32_t)((ch + 1) & 1) * STAGE;
        const uint32_t at = stc + a_base;
        const uint32_t bt = stc + A_TILE + b_base;
        const bool pf = (ch + 1) < NC;
        const int k1 = (ch + 1) << 5;

        // prefetch next chunk (A 4 + B 4 float4), overlapping the MMA block
        float4 av[4], bv[4];
        if (pf) {
            #pragma unroll
            for (int it = 0; it < 4; it++)
                av[it] = *reinterpret_cast<const float4*>(Agp + k1 + it * rstep);
            #pragma unroll
            for (int it = 0; it < 4; it++)
                bv[it] = bok[it] ? *reinterpret_cast<const float4*>(Bgp + k1 + it * rstep)
                                 : make_float4(0.f, 0.f, 0.f, 0.f);
        }

        DO_KC(0)

        if (pf) {
            #pragma unroll
            for (int it = 0; it < 4; it++) {
                uint32_t h0, h1; cvt_hi(av[it], h0, h1);
                sts64(stn + sts_off + (uint32_t)(it * 32 * T_STRIDE), h0, h1);
            }
            #pragma unroll
            for (int it = 0; it < 4; it++) {
                bsum[it] += sq4(bv[it]);
                uint32_t h0, h1; cvt_hi(bv[it], h0, h1);
                sts64(stn + A_TILE + sts_off + (uint32_t)(it * 32 * T_STRIDE), h0, h1);
            }
        }

        DO_KC(1)

        __syncthreads();
    }

    // ---- per-row inverse norms (8 lanes per row: xor 1,2,4) -----------------------
    float* s_inv = reinterpret_cast<float*>(smem + OFF_INV);
    #pragma unroll
    for (int it = 0; it < 4; it++) {
        float v = bsum[it];
        v += __shfl_xor_sync(0xffffffffu, v, 1);
        v += __shfl_xor_sync(0xffffffffu, v, 2);
        v += __shfl_xor_sync(0xffffffffu, v, 4);
        if (c8 == 0)
            s_inv[r0 + 32 * it] = (v > 0.f) ? rsqrtf(v) : 0.f;
    }
    __syncthreads();

    // ---- epilogue: per-(row, 32-col stripe) top-4 of scaled scores ----------------
    {
        const int qr = l >> 2;
        const int qc = (l & 3) * 2;
        const int stripe = blockIdx.y * 4 + wn;
        #pragma unroll
        for (int mi = 0; mi < 4; mi++) {
            #pragma unroll
            for (int h = 0; h < 2; h++) {
                float v[4]; int id[4];
                #pragma unroll
                for (int j = 0; j < 4; j++) { v[j] = -FLT_MAX; id[j] = 0; }
                #pragma unroll
                for (int ni = 0; ni < 4; ni++) {
                    const int nloc = wn * 32 + ni * 8 + qc;
                    const int ng = n0 + nloc;
                    const float* d = acc[mi][ni];
                    float s0 = (ng     < N_BANK) ? d[2 * h]     * s_inv[nloc]     : -FLT_MAX;
                    float s1 = (ng + 1 < N_BANK) ? d[2 * h + 1] * s_inv[nloc + 1] : -FLT_MAX;
                    ins4(s0, ng,     v, id);
                    ins4(s1, ng + 1, v, id);
                }
                #pragma unroll
                for (int o = 1; o <= 2; o <<= 1) {
                    float tv[4]; int ti[4];
                    #pragma unroll
                    for (int j = 0; j < 4; j++) { tv[j] = v[j]; ti[j] = id[j]; }
                    #pragma unroll
                    for (int j = 0; j < 4; j++) {
                        float ov = __shfl_xor_sync(0xffffffffu, tv[j], o);
                        int   oi = __shfl_xor_sync(0xffffffffu, ti[j], o);
                        ins4(ov, oi, v, id);
                    }
                }
                if ((l & 3) == 0) {
                    const int row = m0 + wm * 64 + mi * 16 + qr + 8 * h;
                    float2* dp = selb + ((size_t)row * NSTRIPE_PAD + stripe) * 4;
                    #pragma unroll
                    for (int j = 0; j < 4; j++)
                        dp[j] = make_float2(v[j], __int_as_float(id[j]));
                }
            }
        }
    }
}

// ---------------- 2) merged finalsel: both branches, one launch ----------------
__global__ void finalsel_kernel(const float* __restrict__ fc, const float* __restrict__ sem,
                                const float* __restrict__ fd, const float* __restrict__ dst,
                                const float* __restrict__ metrics,
                                float* __restrict__ out)
{
    __shared__ float sv[256 * 4];
    __shared__ int   si[256 * 4];
    __shared__ float sv2[32 * 8];
    __shared__ int   si2[32 * 8];
    __shared__ int   ci[NCAND];
    __shared__ float ss[NCAND];

    const int row = blockIdx.x;
    const int tid = threadIdx.x;
    float total = 0.f;          // accumulated by thread 0 across branches

    #pragma unroll 1
    for (int br = 0; br < 2; br++) {
        const float* Aq   = br ? fd  : fc;
        const float* Bank = br ? dst : sem;
        const int K = br ? DIM_D : DIM_S;
        const float4* base4 = reinterpret_cast<const float4*>(
            g_sel + (size_t)br * SELSZ + (size_t)row * NSTRIPE_PAD * 4);
        const int nf4 = NSTRIPE_PAD * 4 / 2;      // 3136

        // phase 1: per-thread top-4 with two independent chains (MLP=2)
        float va[4], vb[4]; int ia[4], ib[4];
        #pragma unroll
        for (int j = 0; j < 4; j++) { va[j] = vb[j] = -FLT_MAX; ia[j] = ib[j] = 0; }
        for (int i = tid; i < nf4; i += 512) {
            float4 x = base4[i];
            const bool g2 = (i + 256) < nf4;
            float4 y = g2 ? base4[i + 256] : make_float4(-FLT_MAX, 0.f, -FLT_MAX, 0.f);
            ins4(x.x, __float_as_int(x.y), va, ia);
            ins4(x.z, __float_as_int(x.w), va, ia);
            ins4(y.x, __float_as_int(y.y), vb, ib);
            ins4(y.z, __float_as_int(y.w), vb, ib);
        }
        #pragma unroll
        for (int j = 0; j < 4; j++) ins4(vb[j], ib[j], va, ia);
        #pragma unroll
        for (int j = 0; j < 4; j++) { sv[tid * 4 + j] = va[j]; si[tid * 4 + j] = ia[j]; }
        __syncthreads();

        // phase 2: warp-0 funnel 1024 -> 256
        if (tid < 32) {
            float mv[8]; int mi[8];
            #pragma unroll
            for (int j = 0; j < 8; j++) { mv[j] = -FLT_MAX; mi[j] = 0; }
            for (int e = tid; e < 1024; e += 32)
                ins_n(sv[e], si[e], mv, mi, 8);
            #pragma unroll
            for (int j = 0; j < 8; j++) { sv2[tid * 8 + j] = mv[j]; si2[tid * 8 + j] = mi[j]; }
        }
        __syncthreads();

        // phase 3: thread 0 -> top-16 candidates
        if (tid == 0) {
            float mv[NCAND]; int mi[NCAND];
            #pragma unroll
            for (int j = 0; j < NCAND; j++) { mv[j] = -FLT_MAX; mi[j] = 0; }
            for (int e = 0; e < 256; e++)
                ins_n(sv2[e], si2[e], mv, mi, NCAND);
            #pragma unroll
            for (int j = 0; j < NCAND; j++) ci[j] = mi[j];
        }
        __syncthreads();

        // phase 4: exact fp32 rescore (2 candidates per warp, MLP=2 inner)
        {
            const int wp = tid >> 5, l = tid & 31;
            const float4* q4 = reinterpret_cast<const float4*>(Aq + (size_t)row * K);
            const int kv = K >> 2;
            for (int c = wp; c < NCAND; c += 8) {
                const int idx = ci[c];
                const float4* b4 = reinterpret_cast<const float4*>(Bank + (size_t)idx * K);
                float d0 = 0.f, s0 = 0.f, d1 = 0.f, s1 = 0.f;
                for (int i = l; i < kv; i += 64) {
                    float4 b = b4[i], q = q4[i];
                    float4 b2, q2;
                    const bool g2 = (i + 32) < kv;
                    if (g2) { b2 = b4[i + 32]; q2 = q4[i + 32]; }
                    d0 += q.x * b.x + q.y * b.y + q.z * b.z + q.w * b.w;
                    s0 += b.x * b.x + b.y * b.y + b.z * b.z + b.w * b.w;
                    if (g2) {
                        d1 += q2.x * b2.x + q2.y * b2.y + q2.z * b2.z + q2.w * b2.w;
                        s1 += b2.x * b2.x + b2.y * b2.y + b2.z * b2.z + b2.w * b2.w;
                    }
                }
                float dot = d0 + d1, bsq = s0 + s1;
                #pragma unroll
                for (int o = 16; o; o >>= 1) {
                    dot += __shfl_xor_sync(0xffffffffu, dot, o);
                    bsq += __shfl_xor_sync(0xffffffffu, bsq, o);
                }
                if (l == 0) ss[c] = dot * rsqrtf(bsq);
            }
        }
        __syncthreads();

        // phase 5: exact top-9 + metrics sum for this branch
        if (tid == 0) {
            float v9[KTOP]; int id9[KTOP];
            #pragma unroll
            for (int j = 0; j < KTOP; j++) { v9[j] = -FLT_MAX; id9[j] = 0; }
            #pragma unroll
            for (int c = 0; c < NCAND; c++)
                ins_n(ss[c], ci[c], v9, id9, KTOP);
            #pragma unroll
            for (int j = 0; j < KTOP; j++) total += metrics[id9[j]];
        }
        __syncthreads();   // before smem reuse by next branch
    }

    if (tid == 0)
        out[row] = total * (1.f / (2.f * KTOP));
}

// ---------------- launch ------------------------------------------------------
extern "C" void kernel_launch(void* const* d_in, const int* in_sizes, int n_in,
                              void* d_out, int out_size) {
    const float* f_content    = nullptr;
    const float* f_distorsion = nullptr;
    const float* sem_bank     = nullptr;
    const float* dst_bank     = nullptr;
    const float* metrics      = nullptr;
    for (int i = 0; i < n_in; i++) {
        switch (in_sizes[i]) {
            case B_Q * DIM_S:    f_content    = (const float*)d_in[i]; break;
            case B_Q * DIM_D:    f_distorsion = (const float*)d_in[i]; break;
            case N_BANK * DIM_S: sem_bank     = (const float*)d_in[i]; break;
            case N_BANK * DIM_D: dst_bank     = (const float*)d_in[i]; break;
            case N_BANK:         metrics      = (const float*)d_in[i]; break;
            default: break; // scalar K (=9) compiled in
        }
    }
    float* out = (float*)d_out;

    cudaFuncSetAttribute(gemm_hmma_kernel,
                         cudaFuncAttributeMaxDynamicSharedMemorySize, SMEM_TOTAL);

    // x = M (fastest, L2-shares B stripe), y = N, z = branch
    dim3 grid(B_Q / TILE_M, (N_BANK + TILE_N - 1) / TILE_N, 2);   // (2, 391, 2)

    gemm_hmma_kernel<<<grid, 256, SMEM_TOTAL>>>(f_content, sem_bank,
                                                f_distorsion, dst_bank);
    finalsel_kernel<<<B_Q, 256>>>(f_content, sem_bank, f_distorsion, dst_bank,
                                  metrics, out);
}